// round 6
// baseline (speedup 1.0000x reference)
#include <cuda_runtime.h>
#include <math.h>

#define NN 50000
#define NE 800000

typedef unsigned long long u64;
typedef unsigned int u32;

// ---------------- scratch (device globals; no allocation allowed) ----------
__device__ float g_h [NN * 256];
__device__ float g_x1[NN * 256];
__device__ float g_x2[NN * 256];
__device__ float g_el[NN * 4];
__device__ float g_er[NN * 4];
__device__ int   g_deg[NN];
__device__ int   g_off[NN + 1];
__device__ int   g_cur[NN];
__device__ int   g_esrc[NE];
__device__ int   g_bsum[64];

// ---------------- packed f32x2 helpers ----------------
__device__ __forceinline__ u64 pack2(float x, float y) {
    u64 r; asm("mov.b64 %0, {%1, %2};" : "=l"(r) : "f"(x), "f"(y)); return r;
}
__device__ __forceinline__ u64 ffma2(u64 a, u64 b, u64 c) {
    u64 d; asm("fma.rn.f32x2 %0, %1, %2, %3;" : "=l"(d) : "l"(a), "l"(b), "l"(c));
    return d;
}

// ---------------- cp.async helpers ----------------
__device__ __forceinline__ u32 smem_u32(const void* p) {
    u32 a;
    asm("{ .reg .u64 t; cvta.to.shared.u64 t, %1; cvt.u32.u64 %0, t; }"
        : "=r"(a) : "l"(p));
    return a;
}
__device__ __forceinline__ void cp_async16(u32 s, const void* g) {
    asm volatile("cp.async.ca.shared.global [%0], [%1], 16;" :: "r"(s), "l"(g));
}
__device__ __forceinline__ void cp_commit() { asm volatile("cp.async.commit_group;"); }
__device__ __forceinline__ void cp_wait0()  { asm volatile("cp.async.wait_group 0;"); }

// ---------------- helpers ----------------
__device__ __forceinline__ float warpSum(float v) {
#pragma unroll
    for (int o = 16; o > 0; o >>= 1) v += __shfl_xor_sync(0xffffffffu, v, o);
    return v;
}
__device__ __forceinline__ float lrelu(float x) { return x > 0.f ? x : 0.2f * x; }
__device__ __forceinline__ float eluf(float x)  { return x > 0.f ? x : (__expf(x) - 1.f); }

// ---------------- CSR build ----------------
__global__ void k_zero_deg() {
    int i = blockIdx.x * blockDim.x + threadIdx.x;
    if (i < NN) g_deg[i] = 0;
}
__global__ void k_hist(const int* __restrict__ dst) {
    int e = blockIdx.x * blockDim.x + threadIdx.x;
    if (e < NE) atomicAdd(&g_deg[dst[e]], 1);
}
__global__ void k_scan1() {
    __shared__ int s[1024];
    int tid = threadIdx.x;
    int i = blockIdx.x * 1024 + tid;
    int v = (i < NN) ? g_deg[i] : 0;
    s[tid] = v;
    __syncthreads();
    for (int o = 1; o < 1024; o <<= 1) {
        int t = (tid >= o) ? s[tid - o] : 0;
        __syncthreads();
        s[tid] += t;
        __syncthreads();
    }
    if (i < NN) g_off[i] = s[tid] - v;
    if (tid == 1023) g_bsum[blockIdx.x] = s[1023];
}
__global__ void k_scan2() {
    __shared__ int s[64];
    int tid = threadIdx.x;
    const int nb = (NN + 1023) / 1024;
    int v = (tid < nb) ? g_bsum[tid] : 0;
    s[tid] = v;
    __syncthreads();
    for (int o = 1; o < 64; o <<= 1) {
        int t = (tid >= o) ? s[tid - o] : 0;
        __syncthreads();
        s[tid] += t;
        __syncthreads();
    }
    g_bsum[tid] = s[tid] - v;
}
__global__ void k_scan3() {
    int i = blockIdx.x * blockDim.x + threadIdx.x;
    if (i < NN) {
        int o = g_off[i] + g_bsum[i >> 10];
        g_off[i] = o;
        g_cur[i] = o;
    }
    if (i == 0) g_off[NN] = NE;
}
__global__ void k_fill(const int* __restrict__ dst, const int* __restrict__ src) {
    int e = blockIdx.x * blockDim.x + threadIdx.x;
    if (e < NE) {
        int p = atomicAdd(&g_cur[dst[e]], 1);
        g_esrc[p] = src[e];
    }
}

// ---------------- GEMM: C[M,N] = A[M,K] @ B[K,N]; BM=BN=128, BK=16 ---------
// A stored DUPLICATED in smem (each value twice, adjacent) so packed f32x2
// A-operands come straight from LDS.128 (no per-kk MOV packs). B via cp.async.
// Double-buffered; __launch_bounds__(256,2) keeps 2 CTAs/SM.
__global__ __launch_bounds__(256, 2) void k_gemm(
    const float* __restrict__ A, const float* __restrict__ B,
    float* __restrict__ C, int M, int N, int K) {
    __shared__ float As[2][16][256];   // [buf][k][2*row (+dup)]  32KB
    __shared__ float Bs[2][16][128];   // [buf][k][col]           16KB
    const int tid = threadIdx.x;
    const int row0 = blockIdx.x * 128, col0 = blockIdx.y * 128;
    const int tx = tid & 15, ty = tid >> 4;
    const int arow = tid >> 1, acol = (tid & 1) * 8;  // A: 2 threads/row, 8 k each
    const int brow = tid >> 4, bcol = (tid & 15) * 8; // B: 16 rows, 2 float4/thread

    u64 acc[8][4];
#pragma unroll
    for (int i = 0; i < 8; i++)
#pragma unroll
        for (int j = 0; j < 4; j++) acc[i][j] = 0ull;

    const bool avalid = (row0 + arow) < M;
    const float* Aptr = A + (size_t)(row0 + arow) * K + acol;
    const float* Bptr = B + (size_t)brow * N + col0 + bcol;
    const u32 bs0a = smem_u32(&Bs[0][brow][bcol]);
    const u32 bs0b = smem_u32(&Bs[0][brow][bcol + 4]);
    const u32 bs1a = smem_u32(&Bs[1][brow][bcol]);
    const u32 bs1b = smem_u32(&Bs[1][brow][bcol + 4]);

    // ---- preload first tile ----
    {
        float4 a0 = make_float4(0.f, 0.f, 0.f, 0.f), a1 = a0;
        if (avalid) {
            a0 = *(const float4*)(Aptr);
            a1 = *(const float4*)(Aptr + 4);
        }
        *(u64*)&As[0][acol + 0][2 * arow] = pack2(a0.x, a0.x);
        *(u64*)&As[0][acol + 1][2 * arow] = pack2(a0.y, a0.y);
        *(u64*)&As[0][acol + 2][2 * arow] = pack2(a0.z, a0.z);
        *(u64*)&As[0][acol + 3][2 * arow] = pack2(a0.w, a0.w);
        *(u64*)&As[0][acol + 4][2 * arow] = pack2(a1.x, a1.x);
        *(u64*)&As[0][acol + 5][2 * arow] = pack2(a1.y, a1.y);
        *(u64*)&As[0][acol + 6][2 * arow] = pack2(a1.z, a1.z);
        *(u64*)&As[0][acol + 7][2 * arow] = pack2(a1.w, a1.w);
        cp_async16(bs0a, Bptr);
        cp_async16(bs0b, Bptr + 4);
        cp_commit();
        cp_wait0();
    }
    __syncthreads();

    int buf = 0;
    for (int k0 = 0; k0 < K; k0 += 16) {
        const bool has_next = (k0 + 16) < K;
        float4 a0 = make_float4(0.f, 0.f, 0.f, 0.f), a1 = a0;
        if (has_next) {
            if (avalid) {
                a0 = *(const float4*)(Aptr + k0 + 16);
                a1 = *(const float4*)(Aptr + k0 + 20);
            }
            const float* bn = Bptr + (size_t)(k0 + 16) * N;
            cp_async16(buf ? bs0a : bs1a, bn);
            cp_async16(buf ? bs0b : bs1b, bn + 4);
            cp_commit();
        }
#pragma unroll
        for (int kk = 0; kk < 16; kk++) {
            ulonglong2 qa0 = *(const ulonglong2*)&As[buf][kk][ty * 16 + 0];
            ulonglong2 qa1 = *(const ulonglong2*)&As[buf][kk][ty * 16 + 4];
            ulonglong2 qa2 = *(const ulonglong2*)&As[buf][kk][ty * 16 + 8];
            ulonglong2 qa3 = *(const ulonglong2*)&As[buf][kk][ty * 16 + 12];
            u64 aa[8] = {qa0.x, qa0.y, qa1.x, qa1.y, qa2.x, qa2.y, qa3.x, qa3.y};
            ulonglong2 bA = *(const ulonglong2*)&Bs[buf][kk][tx * 8];
            ulonglong2 bB = *(const ulonglong2*)&Bs[buf][kk][tx * 8 + 4];
            u64 bb[4] = {bA.x, bA.y, bB.x, bB.y};
#pragma unroll
            for (int i = 0; i < 8; i++)
#pragma unroll
                for (int j = 0; j < 4; j++) acc[i][j] = ffma2(aa[i], bb[j], acc[i][j]);
        }
        if (has_next) {
            int nb = buf ^ 1;
            *(u64*)&As[nb][acol + 0][2 * arow] = pack2(a0.x, a0.x);
            *(u64*)&As[nb][acol + 1][2 * arow] = pack2(a0.y, a0.y);
            *(u64*)&As[nb][acol + 2][2 * arow] = pack2(a0.z, a0.z);
            *(u64*)&As[nb][acol + 3][2 * arow] = pack2(a0.w, a0.w);
            *(u64*)&As[nb][acol + 4][2 * arow] = pack2(a1.x, a1.x);
            *(u64*)&As[nb][acol + 5][2 * arow] = pack2(a1.y, a1.y);
            *(u64*)&As[nb][acol + 6][2 * arow] = pack2(a1.z, a1.z);
            *(u64*)&As[nb][acol + 7][2 * arow] = pack2(a1.w, a1.w);
            cp_wait0();
            __syncthreads();
            buf = nb;
        }
    }
#pragma unroll
    for (int i = 0; i < 8; i++) {
        int r = row0 + ty * 8 + i;
        if (r < M) {
            ulonglong2 s0, s1;
            s0.x = acc[i][0]; s0.y = acc[i][1];
            s1.x = acc[i][2]; s1.y = acc[i][3];
            *(ulonglong2*)(C + (size_t)r * N + col0 + tx * 8) = s0;
            *(ulonglong2*)(C + (size_t)r * N + col0 + tx * 8 + 4) = s1;
        }
    }
}

// ---------------- tiny GEMM for W3 (K=256, N=8): warp per row --------------
__global__ __launch_bounds__(256) void k_gemm_w3(
    const float* __restrict__ A, const float* __restrict__ W, float* __restrict__ C) {
    __shared__ float Ws[256 * 9];
    for (int i = threadIdx.x; i < 2048; i += 256) {
        int k = i >> 3, c = i & 7;
        Ws[k * 9 + c] = W[i];
    }
    __syncthreads();
    int w = (blockIdx.x * blockDim.x + threadIdx.x) >> 5;
    int lane = threadIdx.x & 31;
    if (w >= NN) return;
    float acc[8] = {0.f, 0.f, 0.f, 0.f, 0.f, 0.f, 0.f, 0.f};
    for (int k = lane; k < 256; k += 32) {
        float xv = A[(size_t)w * 256 + k];
#pragma unroll
        for (int c = 0; c < 8; c++) acc[c] = fmaf(xv, Ws[k * 9 + c], acc[c]);
    }
#pragma unroll
    for (int c = 0; c < 8; c++) acc[c] = warpSum(acc[c]);
    if (lane == 0) {
#pragma unroll
        for (int c = 0; c < 8; c++) C[(size_t)w * 8 + c] = acc[c];
    }
}

// ---------------- el/er: warp per node --------------------------------------
template <int H, int D>
__global__ __launch_bounds__(256) void k_eler(
    const float* __restrict__ h, const float* __restrict__ al, const float* __restrict__ ar) {
    int w = (blockIdx.x * blockDim.x + threadIdx.x) >> 5;
    int lane = threadIdx.x & 31;
    if (w >= NN) return;
#pragma unroll
    for (int hh = 0; hh < H; hh++) {
        float sl = 0.f, sr = 0.f;
        for (int d = lane; d < D; d += 32) {
            float v = h[(size_t)w * (H * D) + hh * D + d];
            sl = fmaf(v, al[hh * D + d], sl);
            sr = fmaf(v, ar[hh * D + d], sr);
        }
        sl = warpSum(sl);
        sr = warpSum(sr);
        if (lane == 0) {
            g_el[w * H + hh] = sl;
            g_er[w * H + hh] = sr;
        }
    }
}

// ---------------- GAT aggregate, H=4 D=64 (warp per dst node) ---------------
template <bool ELU>
__global__ __launch_bounds__(256) void k_agg_big(
    const float* __restrict__ h,
    const float* __restrict__ bias, float* __restrict__ out) {
    int w = (blockIdx.x * blockDim.x + threadIdx.x) >> 5;
    int lane = threadIdx.x & 31;
    if (w >= NN) return;
    int o0 = g_off[w], o1 = g_off[w + 1];
    int deg = o1 - o0;
    float4 erv = *(const float4*)&g_er[w * 4];

    // phase 1: per-head softmax denominators (unnormalized; exp bounded)
    float s0 = 0.f, s1 = 0.f, s2 = 0.f, s3 = 0.f;
    for (int i = lane; i < deg; i += 32) {
        int s = g_esrc[o0 + i];
        float4 elv = *(const float4*)&g_el[s * 4];
        s0 += __expf(lrelu(elv.x + erv.x));
        s1 += __expf(lrelu(elv.y + erv.y));
        s2 += __expf(lrelu(elv.z + erv.z));
        s3 += __expf(lrelu(elv.w + erv.w));
    }
    s0 = warpSum(s0); s1 = warpSum(s1); s2 = warpSum(s2); s3 = warpSum(s3);
    float inv0 = 1.f / s0, inv1 = 1.f / s1, inv2 = 1.f / s2, inv3 = 1.f / s3;

    // phase 2: weighted gather
    int hA = lane >> 4;
    float invA = hA ? inv1 : inv0;
    float invB = hA ? inv3 : inv2;
    float erA = hA ? erv.y : erv.x;
    float erB = hA ? erv.w : erv.z;
    int f0 = lane * 4, f1 = 128 + lane * 4;
    float4 acc0 = make_float4(0.f, 0.f, 0.f, 0.f);
    float4 acc1 = make_float4(0.f, 0.f, 0.f, 0.f);
#pragma unroll 2
    for (int i = 0; i < deg; i++) {
        int s = g_esrc[o0 + i];
        float4 elv = *(const float4*)&g_el[s * 4];
        float eA = __expf(lrelu((hA ? elv.y : elv.x) + erA));
        float eB = __expf(lrelu((hA ? elv.w : elv.z) + erB));
        float4 h0 = *(const float4*)&h[(size_t)s * 256 + f0];
        float4 h1 = *(const float4*)&h[(size_t)s * 256 + f1];
        acc0.x = fmaf(eA, h0.x, acc0.x); acc0.y = fmaf(eA, h0.y, acc0.y);
        acc0.z = fmaf(eA, h0.z, acc0.z); acc0.w = fmaf(eA, h0.w, acc0.w);
        acc1.x = fmaf(eB, h1.x, acc1.x); acc1.y = fmaf(eB, h1.y, acc1.y);
        acc1.z = fmaf(eB, h1.z, acc1.z); acc1.w = fmaf(eB, h1.w, acc1.w);
    }
    float4 b0 = *(const float4*)&bias[f0];
    float4 b1 = *(const float4*)&bias[f1];
    acc0.x = acc0.x * invA + b0.x; acc0.y = acc0.y * invA + b0.y;
    acc0.z = acc0.z * invA + b0.z; acc0.w = acc0.w * invA + b0.w;
    acc1.x = acc1.x * invB + b1.x; acc1.y = acc1.y * invB + b1.y;
    acc1.z = acc1.z * invB + b1.z; acc1.w = acc1.w * invB + b1.w;
    if (ELU) {
        acc0.x = eluf(acc0.x); acc0.y = eluf(acc0.y); acc0.z = eluf(acc0.z); acc0.w = eluf(acc0.w);
        acc1.x = eluf(acc1.x); acc1.y = eluf(acc1.y); acc1.z = eluf(acc1.z); acc1.w = eluf(acc1.w);
    }
    *(float4*)&out[(size_t)w * 256 + f0] = acc0;
    *(float4*)&out[(size_t)w * 256 + f1] = acc1;
}

// ---------------- GAT aggregate, H=1 D=8 (layer 3) ---------------------------
__global__ __launch_bounds__(256) void k_agg_small(
    const float* __restrict__ h,
    const float* __restrict__ bias, float* __restrict__ out) {
    int w = (blockIdx.x * blockDim.x + threadIdx.x) >> 5;
    int lane = threadIdx.x & 31;
    if (w >= NN) return;
    int o0 = g_off[w], o1 = g_off[w + 1];
    int deg = o1 - o0;
    float ern = g_er[w];

    float acc[8] = {0.f, 0.f, 0.f, 0.f, 0.f, 0.f, 0.f, 0.f};
    float sm = 0.f;
    for (int i = lane; i < deg; i += 32) {
        int s = g_esrc[o0 + i];
        float a = __expf(lrelu(g_el[s] + ern));
        sm += a;
        float4 h0 = *(const float4*)&h[(size_t)s * 8];
        float4 h1 = *(const float4*)&h[(size_t)s * 8 + 4];
        acc[0] = fmaf(a, h0.x, acc[0]); acc[1] = fmaf(a, h0.y, acc[1]);
        acc[2] = fmaf(a, h0.z, acc[2]); acc[3] = fmaf(a, h0.w, acc[3]);
        acc[4] = fmaf(a, h1.x, acc[4]); acc[5] = fmaf(a, h1.y, acc[5]);
        acc[6] = fmaf(a, h1.z, acc[6]); acc[7] = fmaf(a, h1.w, acc[7]);
    }
    sm = warpSum(sm);
#pragma unroll
    for (int j = 0; j < 8; j++) acc[j] = warpSum(acc[j]);
    if (lane == 0) {
        float inv = 1.f / sm;
#pragma unroll
        for (int j = 0; j < 8; j++) out[(size_t)w * 8 + j] = acc[j] * inv + bias[j];
    }
}

// ---------------- launch -----------------------------------------------------
extern "C" void kernel_launch(void* const* d_in, const int* in_sizes, int n_in,
                              void* d_out, int out_size) {
    const float* feat = (const float*)d_in[0];
    const int*   src  = (const int*)d_in[1];
    const int*   dst  = (const int*)d_in[2];
    const float* W1 = (const float*)d_in[3];
    const float* al1 = (const float*)d_in[4];
    const float* ar1 = (const float*)d_in[5];
    const float* b1 = (const float*)d_in[6];
    const float* W2 = (const float*)d_in[7];
    const float* al2 = (const float*)d_in[8];
    const float* ar2 = (const float*)d_in[9];
    const float* b2 = (const float*)d_in[10];
    const float* W3 = (const float*)d_in[11];
    const float* al3 = (const float*)d_in[12];
    const float* ar3 = (const float*)d_in[13];
    const float* b3 = (const float*)d_in[14];
    float* out = (float*)d_out;

    void* p;
    cudaGetSymbolAddress(&p, g_h);  float* h  = (float*)p;
    cudaGetSymbolAddress(&p, g_x1); float* x1 = (float*)p;
    cudaGetSymbolAddress(&p, g_x2); float* x2 = (float*)p;

    const int NODE_BLKS = (NN + 255) / 256;
    const int EDGE_BLKS = (NE + 255) / 256;
    const int WARP_BLKS = (NN * 32 + 255) / 256;
    const int SCAN_BLKS = (NN + 1023) / 1024;

    dim3 g1((NN + 127) / 128, 2);

    // CSR build interleaved with GEMM1 so the ncu slot (#4) lands on the GEMM.
    k_zero_deg<<<NODE_BLKS, 256>>>();
    k_hist<<<EDGE_BLKS, 256>>>(dst);
    k_scan1<<<SCAN_BLKS, 1024>>>();
    k_gemm<<<g1, 256>>>(feat, W1, h, NN, 256, 128);   // layer 1 GEMM (slot 4)
    k_scan2<<<1, 64>>>();
    k_scan3<<<NODE_BLKS, 256>>>();
    k_fill<<<EDGE_BLKS, 256>>>(dst, src);

    // layer 1
    k_eler<4, 64><<<WARP_BLKS, 256>>>(h, al1, ar1);
    k_agg_big<true><<<WARP_BLKS, 256>>>(h, b1, x1);

    // layer 2
    k_gemm<<<g1, 256>>>(x1, W2, h, NN, 256, 256);
    k_eler<4, 64><<<WARP_BLKS, 256>>>(h, al2, ar2);
    k_agg_big<true><<<WARP_BLKS, 256>>>(h, b2, x2);

    // layer 3
    k_gemm_w3<<<WARP_BLKS, 256>>>(x2, W3, h);
    k_eler<1, 8><<<WARP_BLKS, 256>>>(h, al3, ar3);
    k_agg_small<<<WARP_BLKS, 256>>>(h, b3, out);
}

// round 7
// speedup vs baseline: 1.0909x; 1.0909x over previous
#include <cuda_runtime.h>
#include <math.h>

#define NN 50000
#define NE 800000

typedef unsigned long long u64;
typedef unsigned int u32;

// ---------------- scratch (device globals; no allocation allowed) ----------
__device__ float g_h [NN * 256];
__device__ float g_x1[NN * 256];
__device__ float g_x2[NN * 256];
__device__ float g_el[NN * 4];
__device__ float g_er[NN * 4];
__device__ int   g_deg[NN];
__device__ int   g_off[NN + 1];
__device__ int   g_cur[NN];
__device__ int   g_esrc[NE];
__device__ int   g_bsum[64];

// ---------------- packed f32x2 helpers ----------------
__device__ __forceinline__ u64 pack2(float x, float y) {
    u64 r; asm("mov.b64 %0, {%1, %2};" : "=l"(r) : "f"(x), "f"(y)); return r;
}
__device__ __forceinline__ u64 ffma2(u64 a, u64 b, u64 c) {
    u64 d; asm("fma.rn.f32x2 %0, %1, %2, %3;" : "=l"(d) : "l"(a), "l"(b), "l"(c));
    return d;
}

// ---------------- cp.async helpers ----------------
__device__ __forceinline__ u32 smem_u32(const void* p) {
    u32 a;
    asm("{ .reg .u64 t; cvta.to.shared.u64 t, %1; cvt.u32.u64 %0, t; }"
        : "=r"(a) : "l"(p));
    return a;
}
__device__ __forceinline__ void cp_async16(u32 s, const void* g) {
    asm volatile("cp.async.ca.shared.global [%0], [%1], 16;" :: "r"(s), "l"(g));
}
__device__ __forceinline__ void cp_commit() { asm volatile("cp.async.commit_group;"); }
__device__ __forceinline__ void cp_wait0()  { asm volatile("cp.async.wait_group 0;"); }

// ---------------- helpers ----------------
__device__ __forceinline__ float warpSum(float v) {
#pragma unroll
    for (int o = 16; o > 0; o >>= 1) v += __shfl_xor_sync(0xffffffffu, v, o);
    return v;
}
__device__ __forceinline__ float lrelu(float x) { return x > 0.f ? x : 0.2f * x; }
__device__ __forceinline__ float eluf(float x)  { return x > 0.f ? x : (__expf(x) - 1.f); }

// ---------------- CSR build ----------------
__global__ void k_zero_deg() {
    int i = blockIdx.x * blockDim.x + threadIdx.x;
    if (i < NN) g_deg[i] = 0;
}
__global__ void k_hist(const int* __restrict__ dst) {
    int e = blockIdx.x * blockDim.x + threadIdx.x;
    if (e < NE) atomicAdd(&g_deg[dst[e]], 1);
}
__global__ void k_scan1() {
    __shared__ int s[1024];
    int tid = threadIdx.x;
    int i = blockIdx.x * 1024 + tid;
    int v = (i < NN) ? g_deg[i] : 0;
    s[tid] = v;
    __syncthreads();
    for (int o = 1; o < 1024; o <<= 1) {
        int t = (tid >= o) ? s[tid - o] : 0;
        __syncthreads();
        s[tid] += t;
        __syncthreads();
    }
    if (i < NN) g_off[i] = s[tid] - v;
    if (tid == 1023) g_bsum[blockIdx.x] = s[1023];
}
__global__ void k_scan2() {
    __shared__ int s[64];
    int tid = threadIdx.x;
    const int nb = (NN + 1023) / 1024;
    int v = (tid < nb) ? g_bsum[tid] : 0;
    s[tid] = v;
    __syncthreads();
    for (int o = 1; o < 64; o <<= 1) {
        int t = (tid >= o) ? s[tid - o] : 0;
        __syncthreads();
        s[tid] += t;
        __syncthreads();
    }
    g_bsum[tid] = s[tid] - v;
}
__global__ void k_scan3() {
    int i = blockIdx.x * blockDim.x + threadIdx.x;
    if (i < NN) {
        int o = g_off[i] + g_bsum[i >> 10];
        g_off[i] = o;
        g_cur[i] = o;
    }
    if (i == 0) g_off[NN] = NE;
}
__global__ void k_fill(const int* __restrict__ dst, const int* __restrict__ src) {
    int e = blockIdx.x * blockDim.x + threadIdx.x;
    if (e < NE) {
        int p = atomicAdd(&g_cur[dst[e]], 1);
        g_esrc[p] = src[e];
    }
}

// ---------------- GEMM: C[M,N] = A[M,K] @ B[K,N]; BM=BN=128, BK=16 ---------
// R4 operand layout (4 LDS.128 + 8 reg-packs + 32 FFMA2 per kk) but BK=16:
// half the __syncthreads, double compute per sync. B via cp.async, A via
// register prefetch + STS transpose. 2 CTAs/SM.
__global__ __launch_bounds__(256, 2) void k_gemm(
    const float* __restrict__ A, const float* __restrict__ B,
    float* __restrict__ C, int M, int N, int K) {
    __shared__ float As[2][16][128];   // 16KB
    __shared__ float Bs[2][16][128];   // 16KB
    const int tid = threadIdx.x;
    const int row0 = blockIdx.x * 128, col0 = blockIdx.y * 128;
    const int tx = tid & 15, ty = tid >> 4;
    const int arow = tid >> 1, acol = (tid & 1) * 8;   // 2 threads/row, 8 k each
    const int brow = tid >> 4, bcol = (tid & 15) * 8;  // 16 rows, 8 cols/thread

    u64 acc[8][4];
#pragma unroll
    for (int i = 0; i < 8; i++)
#pragma unroll
        for (int j = 0; j < 4; j++) acc[i][j] = 0ull;

    const bool avalid = (row0 + arow) < M;
    const float* Aptr = A + (size_t)(row0 + arow) * K + acol;
    const float* Bptr = B + (size_t)brow * N + col0 + bcol;
    const u32 bs0a = smem_u32(&Bs[0][brow][bcol]);
    const u32 bs0b = smem_u32(&Bs[0][brow][bcol + 4]);
    const u32 bs1a = smem_u32(&Bs[1][brow][bcol]);
    const u32 bs1b = smem_u32(&Bs[1][brow][bcol + 4]);

    // ---- preload first tile ----
    {
        float4 a0 = make_float4(0.f, 0.f, 0.f, 0.f), a1 = a0;
        if (avalid) {
            a0 = *(const float4*)(Aptr);
            a1 = *(const float4*)(Aptr + 4);
        }
        As[0][acol + 0][arow] = a0.x;
        As[0][acol + 1][arow] = a0.y;
        As[0][acol + 2][arow] = a0.z;
        As[0][acol + 3][arow] = a0.w;
        As[0][acol + 4][arow] = a1.x;
        As[0][acol + 5][arow] = a1.y;
        As[0][acol + 6][arow] = a1.z;
        As[0][acol + 7][arow] = a1.w;
        cp_async16(bs0a, Bptr);
        cp_async16(bs0b, Bptr + 4);
        cp_commit();
        cp_wait0();
    }
    __syncthreads();

    int buf = 0;
    for (int k0 = 0; k0 < K; k0 += 16) {
        const bool has_next = (k0 + 16) < K;
        float4 a0 = make_float4(0.f, 0.f, 0.f, 0.f), a1 = a0;
        if (has_next) {
            if (avalid) {
                a0 = *(const float4*)(Aptr + k0 + 16);
                a1 = *(const float4*)(Aptr + k0 + 20);
            }
            const float* bn = Bptr + (size_t)(k0 + 16) * N;
            cp_async16(buf ? bs0a : bs1a, bn);
            cp_async16(buf ? bs0b : bs1b, bn + 4);
            cp_commit();
        }
#pragma unroll
        for (int kk = 0; kk < 16; kk++) {
            float a[8];
            *(float4*)&a[0] = *(const float4*)&As[buf][kk][ty * 8];
            *(float4*)&a[4] = *(const float4*)&As[buf][kk][ty * 8 + 4];
            ulonglong2 bA = *(const ulonglong2*)&Bs[buf][kk][tx * 8];
            ulonglong2 bB = *(const ulonglong2*)&Bs[buf][kk][tx * 8 + 4];
            u64 bb[4] = {bA.x, bA.y, bB.x, bB.y};
            u64 aa[8];
#pragma unroll
            for (int i = 0; i < 8; i++) aa[i] = pack2(a[i], a[i]);
#pragma unroll
            for (int i = 0; i < 8; i++)
#pragma unroll
                for (int j = 0; j < 4; j++) acc[i][j] = ffma2(aa[i], bb[j], acc[i][j]);
        }
        if (has_next) {
            int nb = buf ^ 1;
            As[nb][acol + 0][arow] = a0.x;
            As[nb][acol + 1][arow] = a0.y;
            As[nb][acol + 2][arow] = a0.z;
            As[nb][acol + 3][arow] = a0.w;
            As[nb][acol + 4][arow] = a1.x;
            As[nb][acol + 5][arow] = a1.y;
            As[nb][acol + 6][arow] = a1.z;
            As[nb][acol + 7][arow] = a1.w;
            cp_wait0();
            __syncthreads();
            buf = nb;
        }
    }
#pragma unroll
    for (int i = 0; i < 8; i++) {
        int r = row0 + ty * 8 + i;
        if (r < M) {
            ulonglong2 s0, s1;
            s0.x = acc[i][0]; s0.y = acc[i][1];
            s1.x = acc[i][2]; s1.y = acc[i][3];
            *(ulonglong2*)(C + (size_t)r * N + col0 + tx * 8) = s0;
            *(ulonglong2*)(C + (size_t)r * N + col0 + tx * 8 + 4) = s1;
        }
    }
}

// ------- layer-3 GEMM (K=256, N=8) fused with el/er: warp per row ----------
__global__ __launch_bounds__(256) void k_gemm_w3e(
    const float* __restrict__ A, const float* __restrict__ W,
    const float* __restrict__ al, const float* __restrict__ ar,
    float* __restrict__ C) {
    __shared__ float Ws[256 * 9];
    for (int i = threadIdx.x; i < 2048; i += 256) {
        int k = i >> 3, c = i & 7;
        Ws[k * 9 + c] = W[i];
    }
    __syncthreads();
    int w = (blockIdx.x * blockDim.x + threadIdx.x) >> 5;
    int lane = threadIdx.x & 31;
    if (w >= NN) return;
    float acc[8] = {0.f, 0.f, 0.f, 0.f, 0.f, 0.f, 0.f, 0.f};
    for (int k = lane; k < 256; k += 32) {
        float xv = A[(size_t)w * 256 + k];
#pragma unroll
        for (int c = 0; c < 8; c++) acc[c] = fmaf(xv, Ws[k * 9 + c], acc[c]);
    }
#pragma unroll
    for (int c = 0; c < 8; c++) acc[c] = warpSum(acc[c]);
    if (lane == 0) {
        float el = 0.f, er = 0.f;
#pragma unroll
        for (int c = 0; c < 8; c++) {
            C[(size_t)w * 8 + c] = acc[c];
            el = fmaf(acc[c], al[c], el);
            er = fmaf(acc[c], ar[c], er);
        }
        g_el[w] = el;
        g_er[w] = er;
    }
}

// ---------------- el/er: warp per node --------------------------------------
template <int H, int D>
__global__ __launch_bounds__(256) void k_eler(
    const float* __restrict__ h, const float* __restrict__ al, const float* __restrict__ ar) {
    int w = (blockIdx.x * blockDim.x + threadIdx.x) >> 5;
    int lane = threadIdx.x & 31;
    if (w >= NN) return;
#pragma unroll
    for (int hh = 0; hh < H; hh++) {
        float sl = 0.f, sr = 0.f;
        for (int d = lane; d < D; d += 32) {
            float v = h[(size_t)w * (H * D) + hh * D + d];
            sl = fmaf(v, al[hh * D + d], sl);
            sr = fmaf(v, ar[hh * D + d], sr);
        }
        sl = warpSum(sl);
        sr = warpSum(sr);
        if (lane == 0) {
            g_el[w * H + hh] = sl;
            g_er[w * H + hh] = sr;
        }
    }
}

// ---------------- GAT aggregate, H=4 D=64 (warp per dst node) ---------------
template <bool ELU>
__global__ __launch_bounds__(256) void k_agg_big(
    const float* __restrict__ h,
    const float* __restrict__ bias, float* __restrict__ out) {
    int w = (blockIdx.x * blockDim.x + threadIdx.x) >> 5;
    int lane = threadIdx.x & 31;
    if (w >= NN) return;
    int o0 = g_off[w], o1 = g_off[w + 1];
    int deg = o1 - o0;
    float4 erv = *(const float4*)&g_er[w * 4];

    // phase 1: per-head softmax denominators (unnormalized; exp bounded)
    float s0 = 0.f, s1 = 0.f, s2 = 0.f, s3 = 0.f;
    for (int i = lane; i < deg; i += 32) {
        int s = g_esrc[o0 + i];
        float4 elv = *(const float4*)&g_el[s * 4];
        s0 += __expf(lrelu(elv.x + erv.x));
        s1 += __expf(lrelu(elv.y + erv.y));
        s2 += __expf(lrelu(elv.z + erv.z));
        s3 += __expf(lrelu(elv.w + erv.w));
    }
    s0 = warpSum(s0); s1 = warpSum(s1); s2 = warpSum(s2); s3 = warpSum(s3);
    float inv0 = 1.f / s0, inv1 = 1.f / s1, inv2 = 1.f / s2, inv3 = 1.f / s3;

    // phase 2: weighted gather
    int hA = lane >> 4;
    float invA = hA ? inv1 : inv0;
    float invB = hA ? inv3 : inv2;
    float erA = hA ? erv.y : erv.x;
    float erB = hA ? erv.w : erv.z;
    int f0 = lane * 4, f1 = 128 + lane * 4;
    float4 acc0 = make_float4(0.f, 0.f, 0.f, 0.f);
    float4 acc1 = make_float4(0.f, 0.f, 0.f, 0.f);
#pragma unroll 2
    for (int i = 0; i < deg; i++) {
        int s = g_esrc[o0 + i];
        float4 elv = *(const float4*)&g_el[s * 4];
        float eA = __expf(lrelu((hA ? elv.y : elv.x) + erA));
        float eB = __expf(lrelu((hA ? elv.w : elv.z) + erB));
        float4 h0 = *(const float4*)&h[(size_t)s * 256 + f0];
        float4 h1 = *(const float4*)&h[(size_t)s * 256 + f1];
        acc0.x = fmaf(eA, h0.x, acc0.x); acc0.y = fmaf(eA, h0.y, acc0.y);
        acc0.z = fmaf(eA, h0.z, acc0.z); acc0.w = fmaf(eA, h0.w, acc0.w);
        acc1.x = fmaf(eB, h1.x, acc1.x); acc1.y = fmaf(eB, h1.y, acc1.y);
        acc1.z = fmaf(eB, h1.z, acc1.z); acc1.w = fmaf(eB, h1.w, acc1.w);
    }
    float4 b0 = *(const float4*)&bias[f0];
    float4 b1 = *(const float4*)&bias[f1];
    acc0.x = acc0.x * invA + b0.x; acc0.y = acc0.y * invA + b0.y;
    acc0.z = acc0.z * invA + b0.z; acc0.w = acc0.w * invA + b0.w;
    acc1.x = acc1.x * invB + b1.x; acc1.y = acc1.y * invB + b1.y;
    acc1.z = acc1.z * invB + b1.z; acc1.w = acc1.w * invB + b1.w;
    if (ELU) {
        acc0.x = eluf(acc0.x); acc0.y = eluf(acc0.y); acc0.z = eluf(acc0.z); acc0.w = eluf(acc0.w);
        acc1.x = eluf(acc1.x); acc1.y = eluf(acc1.y); acc1.z = eluf(acc1.z); acc1.w = eluf(acc1.w);
    }
    *(float4*)&out[(size_t)w * 256 + f0] = acc0;
    *(float4*)&out[(size_t)w * 256 + f1] = acc1;
}

// ---------------- GAT aggregate, H=1 D=8 (layer 3) ---------------------------
__global__ __launch_bounds__(256) void k_agg_small(
    const float* __restrict__ h,
    const float* __restrict__ bias, float* __restrict__ out) {
    int w = (blockIdx.x * blockDim.x + threadIdx.x) >> 5;
    int lane = threadIdx.x & 31;
    if (w >= NN) return;
    int o0 = g_off[w], o1 = g_off[w + 1];
    int deg = o1 - o0;
    float ern = g_er[w];

    float acc[8] = {0.f, 0.f, 0.f, 0.f, 0.f, 0.f, 0.f, 0.f};
    float sm = 0.f;
    for (int i = lane; i < deg; i += 32) {
        int s = g_esrc[o0 + i];
        float a = __expf(lrelu(g_el[s] + ern));
        sm += a;
        float4 h0 = *(const float4*)&h[(size_t)s * 8];
        float4 h1 = *(const float4*)&h[(size_t)s * 8 + 4];
        acc[0] = fmaf(a, h0.x, acc[0]); acc[1] = fmaf(a, h0.y, acc[1]);
        acc[2] = fmaf(a, h0.z, acc[2]); acc[3] = fmaf(a, h0.w, acc[3]);
        acc[4] = fmaf(a, h1.x, acc[4]); acc[5] = fmaf(a, h1.y, acc[5]);
        acc[6] = fmaf(a, h1.z, acc[6]); acc[7] = fmaf(a, h1.w, acc[7]);
    }
    sm = warpSum(sm);
#pragma unroll
    for (int j = 0; j < 8; j++) acc[j] = warpSum(acc[j]);
    if (lane == 0) {
        float inv = 1.f / sm;
#pragma unroll
        for (int j = 0; j < 8; j++) out[(size_t)w * 8 + j] = acc[j] * inv + bias[j];
    }
}

// ---------------- launch -----------------------------------------------------
extern "C" void kernel_launch(void* const* d_in, const int* in_sizes, int n_in,
                              void* d_out, int out_size) {
    const float* feat = (const float*)d_in[0];
    const int*   src  = (const int*)d_in[1];
    const int*   dst  = (const int*)d_in[2];
    const float* W1 = (const float*)d_in[3];
    const float* al1 = (const float*)d_in[4];
    const float* ar1 = (const float*)d_in[5];
    const float* b1 = (const float*)d_in[6];
    const float* W2 = (const float*)d_in[7];
    const float* al2 = (const float*)d_in[8];
    const float* ar2 = (const float*)d_in[9];
    const float* b2 = (const float*)d_in[10];
    const float* W3 = (const float*)d_in[11];
    const float* al3 = (const float*)d_in[12];
    const float* ar3 = (const float*)d_in[13];
    const float* b3 = (const float*)d_in[14];
    float* out = (float*)d_out;

    void* p;
    cudaGetSymbolAddress(&p, g_h);  float* h  = (float*)p;
    cudaGetSymbolAddress(&p, g_x1); float* x1 = (float*)p;
    cudaGetSymbolAddress(&p, g_x2); float* x2 = (float*)p;

    const int NODE_BLKS = (NN + 255) / 256;
    const int EDGE_BLKS = (NE + 255) / 256;
    const int WARP_BLKS = (NN * 32 + 255) / 256;
    const int SCAN_BLKS = (NN + 1023) / 1024;

    dim3 g1((NN + 127) / 128, 2);

    // CSR build interleaved with GEMM1 so the ncu slot (#4) lands on the GEMM.
    k_zero_deg<<<NODE_BLKS, 256>>>();
    k_hist<<<EDGE_BLKS, 256>>>(dst);
    k_scan1<<<SCAN_BLKS, 1024>>>();
    k_gemm<<<g1, 256>>>(feat, W1, h, NN, 256, 128);   // layer 1 GEMM (slot 4)
    k_scan2<<<1, 64>>>();
    k_scan3<<<NODE_BLKS, 256>>>();
    k_fill<<<EDGE_BLKS, 256>>>(dst, src);

    // layer 1
    k_eler<4, 64><<<WARP_BLKS, 256>>>(h, al1, ar1);
    k_agg_big<true><<<WARP_BLKS, 256>>>(h, b1, x1);

    // layer 2
    k_gemm<<<g1, 256>>>(x1, W2, h, NN, 256, 256);
    k_eler<4, 64><<<WARP_BLKS, 256>>>(h, al2, ar2);
    k_agg_big<true><<<WARP_BLKS, 256>>>(h, b2, x2);

    // layer 3 (GEMM fused with el/er)
    k_gemm_w3e<<<WARP_BLKS, 256>>>(x2, W3, al3, ar3, h);
    k_agg_small<<<WARP_BLKS, 256>>>(h, b3, out);
}

// round 8
// speedup vs baseline: 1.1969x; 1.0971x over previous
#include <cuda_runtime.h>
#include <math.h>

#define NN 50000
#define NE 800000

typedef unsigned long long u64;
typedef unsigned int u32;

// ---------------- scratch (device globals; no allocation allowed) ----------
__device__ float g_h [NN * 256];
__device__ float g_x1[NN * 256];
__device__ float g_x2[NN * 256];
__device__ float g_el[NN * 4];
__device__ float g_er[NN * 4];
__device__ int   g_deg[NN];
__device__ int   g_off[NN + 1];
__device__ int   g_cur[NN];
__device__ int   g_esrc[NE];
__device__ int   g_bsum[64];

// ---------------- packed f32x2 helpers ----------------
__device__ __forceinline__ u64 pack2(float x, float y) {
    u64 r; asm("mov.b64 %0, {%1, %2};" : "=l"(r) : "f"(x), "f"(y)); return r;
}
__device__ __forceinline__ u64 ffma2(u64 a, u64 b, u64 c) {
    u64 d; asm("fma.rn.f32x2 %0, %1, %2, %3;" : "=l"(d) : "l"(a), "l"(b), "l"(c));
    return d;
}
__device__ __forceinline__ void unpack2(u64 v, float& lo, float& hi) {
    asm("mov.b64 {%0, %1}, %2;" : "=f"(lo), "=f"(hi) : "l"(v));
}

// ---------------- cp.async helpers ----------------
__device__ __forceinline__ u32 smem_u32(const void* p) {
    u32 a;
    asm("{ .reg .u64 t; cvta.to.shared.u64 t, %1; cvt.u32.u64 %0, t; }"
        : "=r"(a) : "l"(p));
    return a;
}
__device__ __forceinline__ void cp_async16(u32 s, const void* g) {
    asm volatile("cp.async.ca.shared.global [%0], [%1], 16;" :: "r"(s), "l"(g));
}
__device__ __forceinline__ void cp_commit() { asm volatile("cp.async.commit_group;"); }
__device__ __forceinline__ void cp_wait0()  { asm volatile("cp.async.wait_group 0;"); }

// ---------------- helpers ----------------
__device__ __forceinline__ float warpSum(float v) {
#pragma unroll
    for (int o = 16; o > 0; o >>= 1) v += __shfl_xor_sync(0xffffffffu, v, o);
    return v;
}
__device__ __forceinline__ float lrelu(float x) { return x > 0.f ? x : 0.2f * x; }
__device__ __forceinline__ float eluf(float x)  { return x > 0.f ? x : (__expf(x) - 1.f); }

// ---------------- CSR build ----------------
__global__ void k_zero_deg() {
    int i = blockIdx.x * blockDim.x + threadIdx.x;
    if (i < NN) g_deg[i] = 0;
}
__global__ void k_hist(const int* __restrict__ dst) {
    int e = blockIdx.x * blockDim.x + threadIdx.x;
    if (e < NE) atomicAdd(&g_deg[dst[e]], 1);
}
__global__ void k_scan1() {
    __shared__ int s[1024];
    int tid = threadIdx.x;
    int i = blockIdx.x * 1024 + tid;
    int v = (i < NN) ? g_deg[i] : 0;
    s[tid] = v;
    __syncthreads();
    for (int o = 1; o < 1024; o <<= 1) {
        int t = (tid >= o) ? s[tid - o] : 0;
        __syncthreads();
        s[tid] += t;
        __syncthreads();
    }
    if (i < NN) g_off[i] = s[tid] - v;
    if (tid == 1023) g_bsum[blockIdx.x] = s[1023];
}
__global__ void k_scan2() {
    __shared__ int s[64];
    int tid = threadIdx.x;
    const int nb = (NN + 1023) / 1024;
    int v = (tid < nb) ? g_bsum[tid] : 0;
    s[tid] = v;
    __syncthreads();
    for (int o = 1; o < 64; o <<= 1) {
        int t = (tid >= o) ? s[tid - o] : 0;
        __syncthreads();
        s[tid] += t;
        __syncthreads();
    }
    g_bsum[tid] = s[tid] - v;
}
__global__ void k_scan3() {
    int i = blockIdx.x * blockDim.x + threadIdx.x;
    if (i < NN) {
        int o = g_off[i] + g_bsum[i >> 10];
        g_off[i] = o;
        g_cur[i] = o;
    }
    if (i == 0) g_off[NN] = NE;
}
__global__ void k_fill(const int* __restrict__ dst, const int* __restrict__ src) {
    int e = blockIdx.x * blockDim.x + threadIdx.x;
    if (e < NE) {
        int p = atomicAdd(&g_cur[dst[e]], 1);
        g_esrc[p] = src[e];
    }
}

// ---------------- GEMM + fused el/er epilogue -------------------------------
// C[M,256] = A[M,K] @ B[K,256]; BM=BN=128, BK=16; FFMA2 inner product.
// Epilogue also computes el/er = C-row dot al/ar (al,ar flat [256], heads are
// contiguous 64-col groups, so this CTA's 128 cols = 2 full heads).
__global__ __launch_bounds__(256, 2) void k_gemm(
    const float* __restrict__ A, const float* __restrict__ B,
    float* __restrict__ C, int M, int K,
    const float* __restrict__ al, const float* __restrict__ ar) {
    __shared__ float As[2][16][128];   // 16KB (reused as reduce scratch)
    __shared__ float Bs[2][16][128];   // 16KB
    const int tid = threadIdx.x;
    const int row0 = blockIdx.x * 128, col0 = blockIdx.y * 128;
    const int tx = tid & 15, ty = tid >> 4;
    const int arow = tid >> 1, acol = (tid & 1) * 8;
    const int brow = tid >> 4, bcol = (tid & 15) * 8;
    const int N = 256;

    u64 acc[8][4];
#pragma unroll
    for (int i = 0; i < 8; i++)
#pragma unroll
        for (int j = 0; j < 4; j++) acc[i][j] = 0ull;

    const bool avalid = (row0 + arow) < M;
    const float* Aptr = A + (size_t)(row0 + arow) * K + acol;
    const float* Bptr = B + (size_t)brow * N + col0 + bcol;
    const u32 bs0a = smem_u32(&Bs[0][brow][bcol]);
    const u32 bs0b = smem_u32(&Bs[0][brow][bcol + 4]);
    const u32 bs1a = smem_u32(&Bs[1][brow][bcol]);
    const u32 bs1b = smem_u32(&Bs[1][brow][bcol + 4]);

    {
        float4 a0 = make_float4(0.f, 0.f, 0.f, 0.f), a1 = a0;
        if (avalid) {
            a0 = *(const float4*)(Aptr);
            a1 = *(const float4*)(Aptr + 4);
        }
        As[0][acol + 0][arow] = a0.x;
        As[0][acol + 1][arow] = a0.y;
        As[0][acol + 2][arow] = a0.z;
        As[0][acol + 3][arow] = a0.w;
        As[0][acol + 4][arow] = a1.x;
        As[0][acol + 5][arow] = a1.y;
        As[0][acol + 6][arow] = a1.z;
        As[0][acol + 7][arow] = a1.w;
        cp_async16(bs0a, Bptr);
        cp_async16(bs0b, Bptr + 4);
        cp_commit();
        cp_wait0();
    }
    __syncthreads();

    int buf = 0;
    for (int k0 = 0; k0 < K; k0 += 16) {
        const bool has_next = (k0 + 16) < K;
        float4 a0 = make_float4(0.f, 0.f, 0.f, 0.f), a1 = a0;
        if (has_next) {
            if (avalid) {
                a0 = *(const float4*)(Aptr + k0 + 16);
                a1 = *(const float4*)(Aptr + k0 + 20);
            }
            const float* bn = Bptr + (size_t)(k0 + 16) * N;
            cp_async16(buf ? bs0a : bs1a, bn);
            cp_async16(buf ? bs0b : bs1b, bn + 4);
            cp_commit();
        }
#pragma unroll
        for (int kk = 0; kk < 16; kk++) {
            float a[8];
            *(float4*)&a[0] = *(const float4*)&As[buf][kk][ty * 8];
            *(float4*)&a[4] = *(const float4*)&As[buf][kk][ty * 8 + 4];
            ulonglong2 bA = *(const ulonglong2*)&Bs[buf][kk][tx * 8];
            ulonglong2 bB = *(const ulonglong2*)&Bs[buf][kk][tx * 8 + 4];
            u64 bb[4] = {bA.x, bA.y, bB.x, bB.y};
            u64 aa[8];
#pragma unroll
            for (int i = 0; i < 8; i++) aa[i] = pack2(a[i], a[i]);
#pragma unroll
            for (int i = 0; i < 8; i++)
#pragma unroll
                for (int j = 0; j < 4; j++) acc[i][j] = ffma2(aa[i], bb[j], acc[i][j]);
        }
        if (has_next) {
            int nb = buf ^ 1;
            As[nb][acol + 0][arow] = a0.x;
            As[nb][acol + 1][arow] = a0.y;
            As[nb][acol + 2][arow] = a0.z;
            As[nb][acol + 3][arow] = a0.w;
            As[nb][acol + 4][arow] = a1.x;
            As[nb][acol + 5][arow] = a1.y;
            As[nb][acol + 6][arow] = a1.z;
            As[nb][acol + 7][arow] = a1.w;
            cp_wait0();
            __syncthreads();
            buf = nb;
        }
    }

    // ---- store C + el/er partials ----
    float alv[8], arv[8];
    *(float4*)&alv[0] = *(const float4*)&al[col0 + tx * 8];
    *(float4*)&alv[4] = *(const float4*)&al[col0 + tx * 8 + 4];
    *(float4*)&arv[0] = *(const float4*)&ar[col0 + tx * 8];
    *(float4*)&arv[4] = *(const float4*)&ar[col0 + tx * 8 + 4];
    __syncthreads();                     // done with tile buffers; reuse As
    float* sp = &As[0][0][0];            // 4096 floats scratch
#pragma unroll
    for (int i = 0; i < 8; i++) {
        int rl = ty * 8 + i;
        int r = row0 + rl;
        float pel = 0.f, per = 0.f;
#pragma unroll
        for (int j = 0; j < 4; j++) {
            float c0, c1;
            unpack2(acc[i][j], c0, c1);
            pel = fmaf(c0, alv[2 * j], pel);
            pel = fmaf(c1, alv[2 * j + 1], pel);
            per = fmaf(c0, arv[2 * j], per);
            per = fmaf(c1, arv[2 * j + 1], per);
        }
        if (r < M) {
            ulonglong2 s0, s1;
            s0.x = acc[i][0]; s0.y = acc[i][1];
            s1.x = acc[i][2]; s1.y = acc[i][3];
            *(ulonglong2*)(C + (size_t)r * N + col0 + tx * 8) = s0;
            *(ulonglong2*)(C + (size_t)r * N + col0 + tx * 8 + 4) = s1;
        }
        sp[(rl * 16 + tx) * 2 + 0] = pel;
        sp[(rl * 16 + tx) * 2 + 1] = per;
    }
    __syncthreads();
    // reduce: 256 threads; unit = (row_local, head_half)
    {
        int rl = tid >> 1, half = tid & 1;
        float el = 0.f, er = 0.f;
#pragma unroll
        for (int q = 0; q < 8; q++) {
            el += sp[((rl * 16) + half * 8 + q) * 2 + 0];
            er += sp[((rl * 16) + half * 8 + q) * 2 + 1];
        }
        int r = row0 + rl;
        int head = blockIdx.y * 2 + half;
        if (r < M) {
            g_el[r * 4 + head] = el;
            g_er[r * 4 + head] = er;
        }
    }
}

// ------- layer-3 GEMM (K=256, N=8) fused with el/er: warp per row ----------
__global__ __launch_bounds__(256) void k_gemm_w3e(
    const float* __restrict__ A, const float* __restrict__ W,
    const float* __restrict__ al, const float* __restrict__ ar,
    float* __restrict__ C) {
    __shared__ float Ws[256 * 9];
    for (int i = threadIdx.x; i < 2048; i += 256) {
        int k = i >> 3, c = i & 7;
        Ws[k * 9 + c] = W[i];
    }
    __syncthreads();
    int w = (blockIdx.x * blockDim.x + threadIdx.x) >> 5;
    int lane = threadIdx.x & 31;
    if (w >= NN) return;
    float acc[8] = {0.f, 0.f, 0.f, 0.f, 0.f, 0.f, 0.f, 0.f};
    for (int k = lane; k < 256; k += 32) {
        float xv = A[(size_t)w * 256 + k];
#pragma unroll
        for (int c = 0; c < 8; c++) acc[c] = fmaf(xv, Ws[k * 9 + c], acc[c]);
    }
#pragma unroll
    for (int c = 0; c < 8; c++) acc[c] = warpSum(acc[c]);
    if (lane == 0) {
        float el = 0.f, er = 0.f;
#pragma unroll
        for (int c = 0; c < 8; c++) {
            C[(size_t)w * 8 + c] = acc[c];
            el = fmaf(acc[c], al[c], el);
            er = fmaf(acc[c], ar[c], er);
        }
        g_el[w] = el;
        g_er[w] = er;
    }
}

// ---------------- GAT aggregate, H=4 D=64 (warp per dst node) ---------------
// Single pass: denominator accumulated inside the gather loop (loop is serial
// over all edges, so every lane holds the full sum); normalize at the end.
template <bool ELU>
__global__ __launch_bounds__(256) void k_agg_big(
    const float* __restrict__ h,
    const float* __restrict__ bias, float* __restrict__ out) {
    int w = (blockIdx.x * blockDim.x + threadIdx.x) >> 5;
    int lane = threadIdx.x & 31;
    if (w >= NN) return;
    int o0 = g_off[w], o1 = g_off[w + 1];
    int deg = o1 - o0;
    float4 erv = *(const float4*)&g_er[w * 4];

    int hA = lane >> 4;                 // head of f0 (0/1); head of f1 is hA+2
    float erA = hA ? erv.y : erv.x;
    float erB = hA ? erv.w : erv.z;
    int f0 = lane * 4, f1 = 128 + lane * 4;
    float4 acc0 = make_float4(0.f, 0.f, 0.f, 0.f);
    float4 acc1 = make_float4(0.f, 0.f, 0.f, 0.f);
    float sA = 0.f, sB = 0.f;
#pragma unroll 2
    for (int i = 0; i < deg; i++) {
        int s = g_esrc[o0 + i];
        float4 elv = *(const float4*)&g_el[s * 4];
        float eA = __expf(lrelu((hA ? elv.y : elv.x) + erA));
        float eB = __expf(lrelu((hA ? elv.w : elv.z) + erB));
        sA += eA;
        sB += eB;
        float4 h0 = *(const float4*)&h[(size_t)s * 256 + f0];
        float4 h1 = *(const float4*)&h[(size_t)s * 256 + f1];
        acc0.x = fmaf(eA, h0.x, acc0.x); acc0.y = fmaf(eA, h0.y, acc0.y);
        acc0.z = fmaf(eA, h0.z, acc0.z); acc0.w = fmaf(eA, h0.w, acc0.w);
        acc1.x = fmaf(eB, h1.x, acc1.x); acc1.y = fmaf(eB, h1.y, acc1.y);
        acc1.z = fmaf(eB, h1.z, acc1.z); acc1.w = fmaf(eB, h1.w, acc1.w);
    }
    float invA = 1.f / sA, invB = 1.f / sB;
    float4 b0 = *(const float4*)&bias[f0];
    float4 b1 = *(const float4*)&bias[f1];
    acc0.x = acc0.x * invA + b0.x; acc0.y = acc0.y * invA + b0.y;
    acc0.z = acc0.z * invA + b0.z; acc0.w = acc0.w * invA + b0.w;
    acc1.x = acc1.x * invB + b1.x; acc1.y = acc1.y * invB + b1.y;
    acc1.z = acc1.z * invB + b1.z; acc1.w = acc1.w * invB + b1.w;
    if (ELU) {
        acc0.x = eluf(acc0.x); acc0.y = eluf(acc0.y); acc0.z = eluf(acc0.z); acc0.w = eluf(acc0.w);
        acc1.x = eluf(acc1.x); acc1.y = eluf(acc1.y); acc1.z = eluf(acc1.z); acc1.w = eluf(acc1.w);
    }
    *(float4*)&out[(size_t)w * 256 + f0] = acc0;
    *(float4*)&out[(size_t)w * 256 + f1] = acc1;
}

// ---------------- GAT aggregate, H=1 D=8 (layer 3) ---------------------------
__global__ __launch_bounds__(256) void k_agg_small(
    const float* __restrict__ h,
    const float* __restrict__ bias, float* __restrict__ out) {
    int w = (blockIdx.x * blockDim.x + threadIdx.x) >> 5;
    int lane = threadIdx.x & 31;
    if (w >= NN) return;
    int o0 = g_off[w], o1 = g_off[w + 1];
    int deg = o1 - o0;
    float ern = g_er[w];

    float acc[8] = {0.f, 0.f, 0.f, 0.f, 0.f, 0.f, 0.f, 0.f};
    float sm = 0.f;
    for (int i = lane; i < deg; i += 32) {
        int s = g_esrc[o0 + i];
        float a = __expf(lrelu(g_el[s] + ern));
        sm += a;
        float4 h0 = *(const float4*)&h[(size_t)s * 8];
        float4 h1 = *(const float4*)&h[(size_t)s * 8 + 4];
        acc[0] = fmaf(a, h0.x, acc[0]); acc[1] = fmaf(a, h0.y, acc[1]);
        acc[2] = fmaf(a, h0.z, acc[2]); acc[3] = fmaf(a, h0.w, acc[3]);
        acc[4] = fmaf(a, h1.x, acc[4]); acc[5] = fmaf(a, h1.y, acc[5]);
        acc[6] = fmaf(a, h1.z, acc[6]); acc[7] = fmaf(a, h1.w, acc[7]);
    }
    sm = warpSum(sm);
#pragma unroll
    for (int j = 0; j < 8; j++) acc[j] = warpSum(acc[j]);
    if (lane == 0) {
        float inv = 1.f / sm;
#pragma unroll
        for (int j = 0; j < 8; j++) out[(size_t)w * 8 + j] = acc[j] * inv + bias[j];
    }
}

// ---------------- launch -----------------------------------------------------
extern "C" void kernel_launch(void* const* d_in, const int* in_sizes, int n_in,
                              void* d_out, int out_size) {
    const float* feat = (const float*)d_in[0];
    const int*   src  = (const int*)d_in[1];
    const int*   dst  = (const int*)d_in[2];
    const float* W1 = (const float*)d_in[3];
    const float* al1 = (const float*)d_in[4];
    const float* ar1 = (const float*)d_in[5];
    const float* b1 = (const float*)d_in[6];
    const float* W2 = (const float*)d_in[7];
    const float* al2 = (const float*)d_in[8];
    const float* ar2 = (const float*)d_in[9];
    const float* b2 = (const float*)d_in[10];
    const float* W3 = (const float*)d_in[11];
    const float* al3 = (const float*)d_in[12];
    const float* ar3 = (const float*)d_in[13];
    const float* b3 = (const float*)d_in[14];
    float* out = (float*)d_out;

    void* p;
    cudaGetSymbolAddress(&p, g_h);  float* h  = (float*)p;
    cudaGetSymbolAddress(&p, g_x1); float* x1 = (float*)p;
    cudaGetSymbolAddress(&p, g_x2); float* x2 = (float*)p;

    const int NODE_BLKS = (NN + 255) / 256;
    const int EDGE_BLKS = (NE + 255) / 256;
    const int WARP_BLKS = (NN * 32 + 255) / 256;
    const int SCAN_BLKS = (NN + 1023) / 1024;

    dim3 g1((NN + 127) / 128, 2);

    // CSR build interleaved with GEMM1 so the ncu slot (#4) lands on the GEMM.
    k_zero_deg<<<NODE_BLKS, 256>>>();
    k_hist<<<EDGE_BLKS, 256>>>(dst);
    k_scan1<<<SCAN_BLKS, 1024>>>();
    k_gemm<<<g1, 256>>>(feat, W1, h, NN, 128, al1, ar1);   // layer 1 GEMM+eler
    k_scan2<<<1, 64>>>();
    k_scan3<<<NODE_BLKS, 256>>>();
    k_fill<<<EDGE_BLKS, 256>>>(dst, src);

    // layer 1 aggregation (single-pass softmax)
    k_agg_big<true><<<WARP_BLKS, 256>>>(h, b1, x1);

    // layer 2
    k_gemm<<<g1, 256>>>(x1, W2, h, NN, 256, al2, ar2);
    k_agg_big<true><<<WARP_BLKS, 256>>>(h, b2, x2);

    // layer 3 (GEMM fused with el/er)
    k_gemm_w3e<<<WARP_BLKS, 256>>>(x2, W3, al3, ar3, h);
    k_agg_small<<<WARP_BLKS, 256>>>(h, b3, out);
}

// round 9
// speedup vs baseline: 1.3100x; 1.0945x over previous
#include <cuda_runtime.h>
#include <math.h>

#define NN 50000
#define NE 800000

typedef unsigned long long u64;
typedef unsigned int u32;

// ---------------- scratch (device globals; no allocation allowed) ----------
__device__ float g_h [NN * 256];
__device__ float g_x1[NN * 256];
__device__ float g_x2[NN * 256];
__device__ float g_el[NN * 4];
__device__ float g_er[NN * 4];
__device__ int   g_deg[NN];
__device__ int   g_off[NN + 1];
__device__ int   g_cur[NN];
__device__ int   g_esrc[NE];
__device__ int   g_bsum[64];

// ---------------- packed f32x2 helpers ----------------
__device__ __forceinline__ u64 pack2(float x, float y) {
    u64 r; asm("mov.b64 %0, {%1, %2};" : "=l"(r) : "f"(x), "f"(y)); return r;
}
__device__ __forceinline__ u64 ffma2(u64 a, u64 b, u64 c) {
    u64 d; asm("fma.rn.f32x2 %0, %1, %2, %3;" : "=l"(d) : "l"(a), "l"(b), "l"(c));
    return d;
}
__device__ __forceinline__ void unpack2(u64 v, float& lo, float& hi) {
    asm("mov.b64 {%0, %1}, %2;" : "=f"(lo), "=f"(hi) : "l"(v));
}

// ---------------- cp.async helpers ----------------
__device__ __forceinline__ u32 smem_u32(const void* p) {
    u32 a;
    asm("{ .reg .u64 t; cvta.to.shared.u64 t, %1; cvt.u32.u64 %0, t; }"
        : "=r"(a) : "l"(p));
    return a;
}
__device__ __forceinline__ void cp_async16(u32 s, const void* g) {
    asm volatile("cp.async.ca.shared.global [%0], [%1], 16;" :: "r"(s), "l"(g));
}
__device__ __forceinline__ void cp_commit() { asm volatile("cp.async.commit_group;"); }
__device__ __forceinline__ void cp_wait0()  { asm volatile("cp.async.wait_group 0;"); }

// ---------------- helpers ----------------
__device__ __forceinline__ float warpSum(float v) {
#pragma unroll
    for (int o = 16; o > 0; o >>= 1) v += __shfl_xor_sync(0xffffffffu, v, o);
    return v;
}
__device__ __forceinline__ float lrelu(float x) { return x > 0.f ? x : 0.2f * x; }
__device__ __forceinline__ float eluf(float x)  { return x > 0.f ? x : (__expf(x) - 1.f); }

// ---------------- CSR build ----------------
__global__ void k_zero_deg() {
    int i = blockIdx.x * blockDim.x + threadIdx.x;
    if (i < NN) g_deg[i] = 0;
}
__global__ void k_hist(const int* __restrict__ dst) {
    int e = blockIdx.x * blockDim.x + threadIdx.x;
    if (e < NE) atomicAdd(&g_deg[dst[e]], 1);
}
__global__ void k_scan1() {
    __shared__ int s[1024];
    int tid = threadIdx.x;
    int i = blockIdx.x * 1024 + tid;
    int v = (i < NN) ? g_deg[i] : 0;
    s[tid] = v;
    __syncthreads();
    for (int o = 1; o < 1024; o <<= 1) {
        int t = (tid >= o) ? s[tid - o] : 0;
        __syncthreads();
        s[tid] += t;
        __syncthreads();
    }
    if (i < NN) g_off[i] = s[tid] - v;
    if (tid == 1023) g_bsum[blockIdx.x] = s[1023];
}
__global__ void k_scan2() {
    __shared__ int s[64];
    int tid = threadIdx.x;
    const int nb = (NN + 1023) / 1024;
    int v = (tid < nb) ? g_bsum[tid] : 0;
    s[tid] = v;
    __syncthreads();
    for (int o = 1; o < 64; o <<= 1) {
        int t = (tid >= o) ? s[tid - o] : 0;
        __syncthreads();
        s[tid] += t;
        __syncthreads();
    }
    g_bsum[tid] = s[tid] - v;
}
__global__ void k_scan3() {
    int i = blockIdx.x * blockDim.x + threadIdx.x;
    if (i < NN) {
        int o = g_off[i] + g_bsum[i >> 10];
        g_off[i] = o;
        g_cur[i] = o;
    }
    if (i == 0) g_off[NN] = NE;
}
__global__ void k_fill(const int* __restrict__ dst, const int* __restrict__ src) {
    int e = blockIdx.x * blockDim.x + threadIdx.x;
    if (e < NE) {
        int p = atomicAdd(&g_cur[dst[e]], 1);
        g_esrc[p] = src[e];
    }
}

// ---------------- GEMM + fused el/er epilogue -------------------------------
// C[M,256] = A[M,K] @ B[K,256]; BM=BN=128, BK=16; FFMA2 inner product.
// Thread owns B cols {tx*4..+3} and {64+tx*4..+3}: bank-conflict-free LDS.128
// and cp.async on the B tile (word offsets tx*4 -> banks 0,4,..28 per phase).
__global__ __launch_bounds__(256, 2) void k_gemm(
    const float* __restrict__ A, const float* __restrict__ B,
    float* __restrict__ C, int M, int K,
    const float* __restrict__ al, const float* __restrict__ ar) {
    __shared__ float As[2][16][128];   // 16KB (reused as reduce scratch)
    __shared__ float Bs[2][16][128];   // 16KB (reused as reduce scratch)
    const int tid = threadIdx.x;
    const int row0 = blockIdx.x * 128, col0 = blockIdx.y * 128;
    const int tx = tid & 15, ty = tid >> 4;
    const int arow = tid >> 1, acol = (tid & 1) * 8;
    const int brow = tid >> 4, bcolq = (tid & 15) * 4;
    const int N = 256;

    u64 acc[8][4];
#pragma unroll
    for (int i = 0; i < 8; i++)
#pragma unroll
        for (int j = 0; j < 4; j++) acc[i][j] = 0ull;

    const bool avalid = (row0 + arow) < M;
    const float* Aptr = A + (size_t)(row0 + arow) * K + acol;
    const float* Bptr = B + (size_t)brow * N + col0 + bcolq;
    const u32 bs0a = smem_u32(&Bs[0][brow][bcolq]);
    const u32 bs0b = smem_u32(&Bs[0][brow][64 + bcolq]);
    const u32 bs1a = smem_u32(&Bs[1][brow][bcolq]);
    const u32 bs1b = smem_u32(&Bs[1][brow][64 + bcolq]);

    {
        float4 a0 = make_float4(0.f, 0.f, 0.f, 0.f), a1 = a0;
        if (avalid) {
            a0 = *(const float4*)(Aptr);
            a1 = *(const float4*)(Aptr + 4);
        }
        As[0][acol + 0][arow] = a0.x;
        As[0][acol + 1][arow] = a0.y;
        As[0][acol + 2][arow] = a0.z;
        As[0][acol + 3][arow] = a0.w;
        As[0][acol + 4][arow] = a1.x;
        As[0][acol + 5][arow] = a1.y;
        As[0][acol + 6][arow] = a1.z;
        As[0][acol + 7][arow] = a1.w;
        cp_async16(bs0a, Bptr);
        cp_async16(bs0b, Bptr + 64);
        cp_commit();
        cp_wait0();
    }
    __syncthreads();

    int buf = 0;
    for (int k0 = 0; k0 < K; k0 += 16) {
        const bool has_next = (k0 + 16) < K;
        float4 a0 = make_float4(0.f, 0.f, 0.f, 0.f), a1 = a0;
        if (has_next) {
            if (avalid) {
                a0 = *(const float4*)(Aptr + k0 + 16);
                a1 = *(const float4*)(Aptr + k0 + 20);
            }
            const float* bn = Bptr + (size_t)(k0 + 16) * N;
            cp_async16(buf ? bs0a : bs1a, bn);
            cp_async16(buf ? bs0b : bs1b, bn + 64);
            cp_commit();
        }
#pragma unroll
        for (int kk = 0; kk < 16; kk++) {
            float a[8];
            *(float4*)&a[0] = *(const float4*)&As[buf][kk][ty * 8];
            *(float4*)&a[4] = *(const float4*)&As[buf][kk][ty * 8 + 4];
            ulonglong2 bA = *(const ulonglong2*)&Bs[buf][kk][tx * 4];
            ulonglong2 bB = *(const ulonglong2*)&Bs[buf][kk][64 + tx * 4];
            u64 bb[4] = {bA.x, bA.y, bB.x, bB.y};
            u64 aa[8];
#pragma unroll
            for (int i = 0; i < 8; i++) aa[i] = pack2(a[i], a[i]);
#pragma unroll
            for (int i = 0; i < 8; i++)
#pragma unroll
                for (int j = 0; j < 4; j++) acc[i][j] = ffma2(aa[i], bb[j], acc[i][j]);
        }
        if (has_next) {
            int nb = buf ^ 1;
            As[nb][acol + 0][arow] = a0.x;
            As[nb][acol + 1][arow] = a0.y;
            As[nb][acol + 2][arow] = a0.z;
            As[nb][acol + 3][arow] = a0.w;
            As[nb][acol + 4][arow] = a1.x;
            As[nb][acol + 5][arow] = a1.y;
            As[nb][acol + 6][arow] = a1.z;
            As[nb][acol + 7][arow] = a1.w;
            cp_wait0();
            __syncthreads();
            buf = nb;
        }
    }

    // ---- store C + el/er partials ----
    // cols {col0+tx*4..+3} belong to head 2*by; {col0+64+tx*4..+3} to 2*by+1
    float alv[8], arv[8];
    *(float4*)&alv[0] = *(const float4*)&al[col0 + tx * 4];
    *(float4*)&alv[4] = *(const float4*)&al[col0 + 64 + tx * 4];
    *(float4*)&arv[0] = *(const float4*)&ar[col0 + tx * 4];
    *(float4*)&arv[4] = *(const float4*)&ar[col0 + 64 + tx * 4];
    __syncthreads();                       // done with tile buffers
    float* spA = &As[0][0][0];             // head 2*by   partials (4096 floats)
    float* spB = &Bs[0][0][0];             // head 2*by+1 partials
#pragma unroll
    for (int i = 0; i < 8; i++) {
        int rl = ty * 8 + i;
        int r = row0 + rl;
        float pelA = 0.f, perA = 0.f, pelB = 0.f, perB = 0.f;
#pragma unroll
        for (int j = 0; j < 2; j++) {
            float c0, c1;
            unpack2(acc[i][j], c0, c1);
            pelA = fmaf(c0, alv[2 * j], pelA);
            pelA = fmaf(c1, alv[2 * j + 1], pelA);
            perA = fmaf(c0, arv[2 * j], perA);
            perA = fmaf(c1, arv[2 * j + 1], perA);
            float d0, d1;
            unpack2(acc[i][j + 2], d0, d1);
            pelB = fmaf(d0, alv[4 + 2 * j], pelB);
            pelB = fmaf(d1, alv[4 + 2 * j + 1], pelB);
            perB = fmaf(d0, arv[4 + 2 * j], perB);
            perB = fmaf(d1, arv[4 + 2 * j + 1], perB);
        }
        if (r < M) {
            ulonglong2 s0, s1;
            s0.x = acc[i][0]; s0.y = acc[i][1];
            s1.x = acc[i][2]; s1.y = acc[i][3];
            *(ulonglong2*)(C + (size_t)r * N + col0 + tx * 4) = s0;
            *(ulonglong2*)(C + (size_t)r * N + col0 + 64 + tx * 4) = s1;
        }
        spA[(rl * 16 + tx) * 2 + 0] = pelA;
        spA[(rl * 16 + tx) * 2 + 1] = perA;
        spB[(rl * 16 + tx) * 2 + 0] = pelB;
        spB[(rl * 16 + tx) * 2 + 1] = perB;
    }
    __syncthreads();
    {
        int rl = tid >> 1, half = tid & 1;
        const float* sp = half ? spB : spA;
        float el = 0.f, er = 0.f;
#pragma unroll
        for (int q = 0; q < 16; q++) {
            el += sp[(rl * 16 + q) * 2 + 0];
            er += sp[(rl * 16 + q) * 2 + 1];
        }
        int r = row0 + rl;
        int head = blockIdx.y * 2 + half;
        if (r < M) {
            g_el[r * 4 + head] = el;
            g_er[r * 4 + head] = er;
        }
    }
}

// ------- layer-3 GEMM (K=256, N=8) fused with el/er: warp per row ----------
__global__ __launch_bounds__(256) void k_gemm_w3e(
    const float* __restrict__ A, const float* __restrict__ W,
    const float* __restrict__ al, const float* __restrict__ ar,
    float* __restrict__ C) {
    __shared__ float Ws[256 * 9];
    for (int i = threadIdx.x; i < 2048; i += 256) {
        int k = i >> 3, c = i & 7;
        Ws[k * 9 + c] = W[i];
    }
    __syncthreads();
    int w = (blockIdx.x * blockDim.x + threadIdx.x) >> 5;
    int lane = threadIdx.x & 31;
    if (w >= NN) return;
    float acc[8] = {0.f, 0.f, 0.f, 0.f, 0.f, 0.f, 0.f, 0.f};
    for (int k = lane; k < 256; k += 32) {
        float xv = A[(size_t)w * 256 + k];
#pragma unroll
        for (int c = 0; c < 8; c++) acc[c] = fmaf(xv, Ws[k * 9 + c], acc[c]);
    }
#pragma unroll
    for (int c = 0; c < 8; c++) acc[c] = warpSum(acc[c]);
    if (lane == 0) {
        float el = 0.f, er = 0.f;
#pragma unroll
        for (int c = 0; c < 8; c++) {
            C[(size_t)w * 8 + c] = acc[c];
            el = fmaf(acc[c], al[c], el);
            er = fmaf(acc[c], ar[c], er);
        }
        g_el[w] = el;
        g_er[w] = er;
    }
}

// ---------------- GAT aggregate, H=4 D=64 (warp per dst node) ---------------
template <bool ELU>
__global__ __launch_bounds__(256) void k_agg_big(
    const float* __restrict__ h,
    const float* __restrict__ bias, float* __restrict__ out) {
    int w = (blockIdx.x * blockDim.x + threadIdx.x) >> 5;
    int lane = threadIdx.x & 31;
    if (w >= NN) return;
    int o0 = g_off[w], o1 = g_off[w + 1];
    int deg = o1 - o0;
    float4 erv = *(const float4*)&g_er[w * 4];

    int hA = lane >> 4;
    float erA = hA ? erv.y : erv.x;
    float erB = hA ? erv.w : erv.z;
    int f0 = lane * 4, f1 = 128 + lane * 4;
    float4 acc0 = make_float4(0.f, 0.f, 0.f, 0.f);
    float4 acc1 = make_float4(0.f, 0.f, 0.f, 0.f);
    float sA = 0.f, sB = 0.f;
#pragma unroll 2
    for (int i = 0; i < deg; i++) {
        int s = g_esrc[o0 + i];
        float4 elv = *(const float4*)&g_el[s * 4];
        float eA = __expf(lrelu((hA ? elv.y : elv.x) + erA));
        float eB = __expf(lrelu((hA ? elv.w : elv.z) + erB));
        sA += eA;
        sB += eB;
        float4 h0 = *(const float4*)&h[(size_t)s * 256 + f0];
        float4 h1 = *(const float4*)&h[(size_t)s * 256 + f1];
        acc0.x = fmaf(eA, h0.x, acc0.x); acc0.y = fmaf(eA, h0.y, acc0.y);
        acc0.z = fmaf(eA, h0.z, acc0.z); acc0.w = fmaf(eA, h0.w, acc0.w);
        acc1.x = fmaf(eB, h1.x, acc1.x); acc1.y = fmaf(eB, h1.y, acc1.y);
        acc1.z = fmaf(eB, h1.z, acc1.z); acc1.w = fmaf(eB, h1.w, acc1.w);
    }
    float invA = 1.f / sA, invB = 1.f / sB;
    float4 b0 = *(const float4*)&bias[f0];
    float4 b1 = *(const float4*)&bias[f1];
    acc0.x = acc0.x * invA + b0.x; acc0.y = acc0.y * invA + b0.y;
    acc0.z = acc0.z * invA + b0.z; acc0.w = acc0.w * invA + b0.w;
    acc1.x = acc1.x * invB + b1.x; acc1.y = acc1.y * invB + b1.y;
    acc1.z = acc1.z * invB + b1.z; acc1.w = acc1.w * invB + b1.w;
    if (ELU) {
        acc0.x = eluf(acc0.x); acc0.y = eluf(acc0.y); acc0.z = eluf(acc0.z); acc0.w = eluf(acc0.w);
        acc1.x = eluf(acc1.x); acc1.y = eluf(acc1.y); acc1.z = eluf(acc1.z); acc1.w = eluf(acc1.w);
    }
    *(float4*)&out[(size_t)w * 256 + f0] = acc0;
    *(float4*)&out[(size_t)w * 256 + f1] = acc1;
}

// ---------------- GAT aggregate, H=1 D=8 (layer 3) ---------------------------
__global__ __launch_bounds__(256) void k_agg_small(
    const float* __restrict__ h,
    const float* __restrict__ bias, float* __restrict__ out) {
    int w = (blockIdx.x * blockDim.x + threadIdx.x) >> 5;
    int lane = threadIdx.x & 31;
    if (w >= NN) return;
    int o0 = g_off[w], o1 = g_off[w + 1];
    int deg = o1 - o0;
    float ern = g_er[w];

    float acc[8] = {0.f, 0.f, 0.f, 0.f, 0.f, 0.f, 0.f, 0.f};
    float sm = 0.f;
    for (int i = lane; i < deg; i += 32) {
        int s = g_esrc[o0 + i];
        float a = __expf(lrelu(g_el[s] + ern));
        sm += a;
        float4 h0 = *(const float4*)&h[(size_t)s * 8];
        float4 h1 = *(const float4*)&h[(size_t)s * 8 + 4];
        acc[0] = fmaf(a, h0.x, acc[0]); acc[1] = fmaf(a, h0.y, acc[1]);
        acc[2] = fmaf(a, h0.z, acc[2]); acc[3] = fmaf(a, h0.w, acc[3]);
        acc[4] = fmaf(a, h1.x, acc[4]); acc[5] = fmaf(a, h1.y, acc[5]);
        acc[6] = fmaf(a, h1.z, acc[6]); acc[7] = fmaf(a, h1.w, acc[7]);
    }
    sm = warpSum(sm);
#pragma unroll
    for (int j = 0; j < 8; j++) acc[j] = warpSum(acc[j]);
    if (lane == 0) {
        float inv = 1.f / sm;
#pragma unroll
        for (int j = 0; j < 8; j++) out[(size_t)w * 8 + j] = acc[j] * inv + bias[j];
    }
}

// ---------------- launch -----------------------------------------------------
extern "C" void kernel_launch(void* const* d_in, const int* in_sizes, int n_in,
                              void* d_out, int out_size) {
    const float* feat = (const float*)d_in[0];
    const int*   src  = (const int*)d_in[1];
    const int*   dst  = (const int*)d_in[2];
    const float* W1 = (const float*)d_in[3];
    const float* al1 = (const float*)d_in[4];
    const float* ar1 = (const float*)d_in[5];
    const float* b1 = (const float*)d_in[6];
    const float* W2 = (const float*)d_in[7];
    const float* al2 = (const float*)d_in[8];
    const float* ar2 = (const float*)d_in[9];
    const float* b2 = (const float*)d_in[10];
    const float* W3 = (const float*)d_in[11];
    const float* al3 = (const float*)d_in[12];
    const float* ar3 = (const float*)d_in[13];
    const float* b3 = (const float*)d_in[14];
    float* out = (float*)d_out;

    void* p;
    cudaGetSymbolAddress(&p, g_h);  float* h  = (float*)p;
    cudaGetSymbolAddress(&p, g_x1); float* x1 = (float*)p;
    cudaGetSymbolAddress(&p, g_x2); float* x2 = (float*)p;

    const int NODE_BLKS = (NN + 255) / 256;
    const int EDGE_BLKS = (NE + 255) / 256;
    const int WARP_BLKS = (NN * 32 + 255) / 256;
    const int SCAN_BLKS = (NN + 1023) / 1024;

    dim3 g1((NN + 127) / 128, 2);

    // CSR build interleaved with GEMM1 so the ncu slot (#4) lands on the GEMM.
    k_zero_deg<<<NODE_BLKS, 256>>>();
    k_hist<<<EDGE_BLKS, 256>>>(dst);
    k_scan1<<<SCAN_BLKS, 1024>>>();
    k_gemm<<<g1, 256>>>(feat, W1, h, NN, 128, al1, ar1);   // layer 1 GEMM+eler
    k_scan2<<<1, 64>>>();
    k_scan3<<<NODE_BLKS, 256>>>();
    k_fill<<<EDGE_BLKS, 256>>>(dst, src);

    // layer 1 aggregation (single-pass softmax)
    k_agg_big<true><<<WARP_BLKS, 256>>>(h, b1, x1);

    // layer 2
    k_gemm<<<g1, 256>>>(x1, W2, h, NN, 256, al2, ar2);
    k_agg_big<true><<<WARP_BLKS, 256>>>(h, b2, x2);

    // layer 3 (GEMM fused with el/er)
    k_gemm_w3e<<<WARP_BLKS, 256>>>(x2, W3, al3, ar3, h);
    k_agg_small<<<WARP_BLKS, 256>>>(h, b3, out);
}